// round 4
// baseline (speedup 1.0000x reference)
#include <cuda_runtime.h>
#include <cstdint>
#include <math.h>

#define S_  2048
#define B_  4
#define H_  2048
#define BS_ 8192
#define NEGV (-1e9f)
#define SCALE_ 0.17677669529663687f

// ---------------- scratch (static __device__, no allocations) ----------------
__device__ __align__(128) float  g_Wcat[128 * H_];                 // 1 MB   [Qa|Ka|Qb|Kb] rows
__device__ __align__(128) float  g_proj[(size_t)BS_ * 128];        // 4 MB   per-token [Qa|Ka|Qb|Kb]
__device__ __align__(128) float2 g_stats[(size_t)8 * S_];          // 128 KB per (slab,row): {max, 1/sum}
__device__ __align__(128) float  g_AO[(size_t)8 * S_ * S_];        // 134 MB attention outputs
__device__ __align__(128) float  g_Y [(size_t)2 * BS_ * 128];      // 8 MB   MLP hidden

// ---------------- f32x2 packed FMA helpers (Blackwell FFMA2) ----------------
__device__ __forceinline__ unsigned long long pk(float lo, float hi) {
    unsigned long long r;
    asm("mov.b64 %0, {%1, %2};" : "=l"(r) : "f"(lo), "f"(hi));
    return r;
}
__device__ __forceinline__ unsigned long long pk2(float v) {
    unsigned long long r;
    asm("mov.b64 %0, {%1, %1};" : "=l"(r) : "f"(v));
    return r;
}
__device__ __forceinline__ void upk(unsigned long long v, float &lo, float &hi) {
    asm("mov.b64 {%0, %1}, %2;" : "=f"(lo), "=f"(hi) : "l"(v));
}
__device__ __forceinline__ void fma2(unsigned long long &d, unsigned long long a, unsigned long long b) {
    asm("fma.rn.f32x2 %0, %1, %2, %0;" : "+l"(d) : "l"(a), "l"(b));
}

__device__ __forceinline__ float gelu_exact(float x) {
    return 0.5f * x * (1.0f + erff(x * 0.7071067811865476f));
}

// ---------------- K0: pack the 4 attention projection weights ----------------
__global__ void pack_w(const float* __restrict__ qa, const float* __restrict__ ka,
                       const float* __restrict__ qb, const float* __restrict__ kb) {
    int i = blockIdx.x * blockDim.x + threadIdx.x;
    if (i >= 128 * H_) return;
    int c = i >> 11;   // /2048
    int k = i & 2047;
    const float* src = (c < 32) ? qa + (size_t)c * H_
                     : (c < 64) ? ka + (size_t)(c - 32) * H_
                     : (c < 96) ? qb + (size_t)(c - 64) * H_
                                : kb + (size_t)(c - 96) * H_;
    g_Wcat[i] = src[k];
}

// ---------------- K1/K4: Out[8192,128] = act(X[8192,2048] @ W[128,2048]^T + b)
// mode 0: X = h,                W = g_Wcat, Out = g_proj,          no bias/act
// mode 1: X = g_AO,             W = Wext,   Out = g_Y,             bias + gelu
// mode 2: X = g_AO + 4*S*S,     W = Wext,   Out = g_Y + BS*128,    bias + gelu
__global__ void __launch_bounds__(256) gemm_h128(const float* __restrict__ Xext,
                                                 const float* __restrict__ Wext,
                                                 const float* __restrict__ bias,
                                                 int mode) {
    const float* X = (mode == 0) ? Xext : (mode == 1) ? g_AO : (g_AO + (size_t)4 * S_ * S_);
    const float* W = (mode == 0) ? g_Wcat : Wext;
    float* Out     = (mode == 0) ? g_proj : (mode == 1) ? g_Y : (g_Y + (size_t)BS_ * 128);
    int act = (mode != 0);

    __shared__ float xs[64][33];
    __shared__ float ws[128][33];
    int tid = threadIdx.x;
    int r0  = blockIdx.x * 64;
    int rg  = tid >> 5;     // 0..7  -> rows rg*8 .. rg*8+7
    int cg  = tid & 31;     // cols cg + 32*j

    unsigned long long acc2[4][4];
    #pragma unroll
    for (int i = 0; i < 4; i++)
        #pragma unroll
        for (int j = 0; j < 4; j++) acc2[i][j] = 0ULL;

    for (int k0 = 0; k0 < H_; k0 += 32) {
        {   // load X tile 64x32
            int row = tid >> 2, kq = (tid & 3) * 8;
            const float4* p = (const float4*)(X + (size_t)(r0 + row) * H_ + k0 + kq);
            float4 v0 = p[0], v1 = p[1];
            xs[row][kq + 0] = v0.x; xs[row][kq + 1] = v0.y; xs[row][kq + 2] = v0.z; xs[row][kq + 3] = v0.w;
            xs[row][kq + 4] = v1.x; xs[row][kq + 5] = v1.y; xs[row][kq + 6] = v1.z; xs[row][kq + 7] = v1.w;
        }
        {   // load W tile 128x32
            int c = tid >> 1, kq = (tid & 1) * 16;
            const float4* p = (const float4*)(W + (size_t)c * H_ + k0 + kq);
            float4 v0 = p[0], v1 = p[1], v2 = p[2], v3 = p[3];
            ws[c][kq + 0] = v0.x; ws[c][kq + 1] = v0.y; ws[c][kq + 2] = v0.z; ws[c][kq + 3] = v0.w;
            ws[c][kq + 4] = v1.x; ws[c][kq + 5] = v1.y; ws[c][kq + 6] = v1.z; ws[c][kq + 7] = v1.w;
            ws[c][kq + 8] = v2.x; ws[c][kq + 9] = v2.y; ws[c][kq +10] = v2.z; ws[c][kq +11] = v2.w;
            ws[c][kq +12] = v3.x; ws[c][kq +13] = v3.y; ws[c][kq +14] = v3.z; ws[c][kq +15] = v3.w;
        }
        __syncthreads();
        #pragma unroll
        for (int kk = 0; kk < 32; kk++) {
            float x0 = xs[rg * 8 + 0][kk], x1 = xs[rg * 8 + 1][kk];
            float x2 = xs[rg * 8 + 2][kk], x3 = xs[rg * 8 + 3][kk];
            float x4 = xs[rg * 8 + 4][kk], x5 = xs[rg * 8 + 5][kk];
            float x6 = xs[rg * 8 + 6][kk], x7 = xs[rg * 8 + 7][kk];
            unsigned long long a0 = pk(x0, x1), a1 = pk(x2, x3), a2 = pk(x4, x5), a3 = pk(x6, x7);
            unsigned long long b0 = pk2(ws[cg      ][kk]);
            unsigned long long b1 = pk2(ws[cg + 32 ][kk]);
            unsigned long long b2 = pk2(ws[cg + 64 ][kk]);
            unsigned long long b3 = pk2(ws[cg + 96 ][kk]);
            fma2(acc2[0][0], a0, b0); fma2(acc2[0][1], a0, b1); fma2(acc2[0][2], a0, b2); fma2(acc2[0][3], a0, b3);
            fma2(acc2[1][0], a1, b0); fma2(acc2[1][1], a1, b1); fma2(acc2[1][2], a1, b2); fma2(acc2[1][3], a1, b3);
            fma2(acc2[2][0], a2, b0); fma2(acc2[2][1], a2, b1); fma2(acc2[2][2], a2, b2); fma2(acc2[2][3], a2, b3);
            fma2(acc2[3][0], a3, b0); fma2(acc2[3][1], a3, b1); fma2(acc2[3][2], a3, b2); fma2(acc2[3][3], a3, b3);
        }
        __syncthreads();
    }

    #pragma unroll
    for (int i2 = 0; i2 < 4; i2++) {
        #pragma unroll
        for (int j = 0; j < 4; j++) {
            float lo, hi; upk(acc2[i2][j], lo, hi);
            int col  = cg + 32 * j;
            int row0 = r0 + rg * 8 + 2 * i2;
            float bsv = bias ? bias[col] : 0.0f;
            float v0 = lo + bsv, v1 = hi + bsv;
            if (act) { v0 = gelu_exact(v0); v1 = gelu_exact(v1); }
            Out[(size_t)row0 * 128 + col]       = v0;
            Out[(size_t)(row0 + 1) * 128 + col] = v1;
        }
    }
}

// ---------------- K2: per-row softmax stats (max, 1/sumexp) ------------------
// grid (S_/32, 8). Block = 256 thr = 8 warps; each warp owns 4 rows.
__global__ void __launch_bounds__(256) softmax_stats(const int* __restrict__ mask) {
    int z = blockIdx.y, a = z >> 2, bb = z & 3;
    int s0 = blockIdx.x * 32;
    int tid = threadIdx.x, lane = tid & 31, w = tid >> 5;

    __shared__ float Qs[32][33];
    __shared__ float Ks[32][33];
    {   // Q rows s0..s0+31 (cols a*64 .. a*64+31) — vector gmem load, scalar smem store
        int row = tid >> 3, j = (tid & 7) * 4;
        float4 v = *(const float4*)(g_proj + (size_t)(bb * S_ + s0 + row) * 128 + a * 64 + j);
        Qs[row][j] = v.x; Qs[row][j + 1] = v.y; Qs[row][j + 2] = v.z; Qs[row][j + 3] = v.w;
    }

    int tmax = s0 + 31;
    float mreg[4] = {NEGV, NEGV, NEGV, NEGV};

    // pass 1: row max
    for (int t0 = 0; t0 <= tmax; t0 += 32) {
        __syncthreads();
        {   int row = tid >> 3, j = (tid & 7) * 4;
            float4 v = *(const float4*)(g_proj + (size_t)(bb * S_ + t0 + row) * 128 + a * 64 + 32 + j);
            Ks[row][j] = v.x; Ks[row][j + 1] = v.y; Ks[row][j + 2] = v.z; Ks[row][j + 3] = v.w;
        }
        __syncthreads();
        int t = t0 + lane;
        int mv = mask[bb * S_ + t];
        #pragma unroll
        for (int rr = 0; rr < 4; rr++) {
            int sl = w * 4 + rr, s = s0 + sl;
            float dot = 0.0f;
            #pragma unroll
            for (int j = 0; j < 32; j++) dot += Qs[sl][j] * Ks[lane][j];
            float x = (t <= s && mv) ? dot * SCALE_ : NEGV;
            mreg[rr] = fmaxf(mreg[rr], x);
        }
    }
    float mfin[4];
    #pragma unroll
    for (int rr = 0; rr < 4; rr++) {
        float m = mreg[rr];
        #pragma unroll
        for (int off = 16; off > 0; off >>= 1)
            m = fmaxf(m, __shfl_xor_sync(0xffffffffu, m, off));
        mfin[rr] = m;
    }

    // pass 2: sum of exp
    float lreg[4] = {0.f, 0.f, 0.f, 0.f};
    for (int t0 = 0; t0 <= tmax; t0 += 32) {
        __syncthreads();
        {   int row = tid >> 3, j = (tid & 7) * 4;
            float4 v = *(const float4*)(g_proj + (size_t)(bb * S_ + t0 + row) * 128 + a * 64 + 32 + j);
            Ks[row][j] = v.x; Ks[row][j + 1] = v.y; Ks[row][j + 2] = v.z; Ks[row][j + 3] = v.w;
        }
        __syncthreads();
        int t = t0 + lane;
        int mv = mask[bb * S_ + t];
        #pragma unroll
        for (int rr = 0; rr < 4; rr++) {
            int sl = w * 4 + rr, s = s0 + sl;
            float dot = 0.0f;
            #pragma unroll
            for (int j = 0; j < 32; j++) dot += Qs[sl][j] * Ks[lane][j];
            float x = (t <= s && mv) ? dot * SCALE_ : NEGV;
            lreg[rr] += __expf(x - mfin[rr]);
        }
    }
    #pragma unroll
    for (int rr = 0; rr < 4; rr++) {
        float l = lreg[rr];
        #pragma unroll
        for (int off = 16; off > 0; off >>= 1)
            l += __shfl_xor_sync(0xffffffffu, l, off);
        if (lane == 0) {
            int s = s0 + w * 4 + rr;
            g_stats[(size_t)z * S_ + s] = make_float2(mfin[rr], 1.0f / l);
        }
    }
}

// ---------------- K3: g_AO = softmax(QK^T) @ h, P regenerated on the fly -----
// 128x128 output tile, k in steps of 16 truncated at m0+128 (causal).
__global__ void __launch_bounds__(256) gemm_pav2(const float* __restrict__ hbase,
                                                 const int* __restrict__ mask) {
    int bxn = blockIdx.x, bym = blockIdx.y, z = blockIdx.z;
    int a = z >> 2, bb = z & 3;
    const float* Bm = hbase + (size_t)bb * S_ * H_;
    float* C = g_AO + (size_t)z * S_ * S_;
    int m0 = bym * 128, n0 = bxn * 128;
    int kmax = m0 + 128;   // P[s][t]==0 exactly for t>s

    __shared__ float Qs[128][33];
    __shared__ float Ks[16][33];
    __shared__ float As[16][132];
    __shared__ float Bs[16][128];
    __shared__ float ms[128];
    __shared__ float il[128];

    int tid = threadIdx.x;
    int tm = tid >> 4, tn = tid & 15;
    int kkA = tid & 15, mgA = (tid >> 4) * 8;

    {   // Q rows m0..m0+127 once — vector gmem loads, scalar smem stores
        int row = tid >> 1, j = (tid & 1) * 16;
        const float4* p = (const float4*)(g_proj + (size_t)(bb * S_ + m0 + row) * 128 + a * 64 + j);
        float4 v0 = p[0], v1 = p[1], v2 = p[2], v3 = p[3];
        Qs[row][j + 0] = v0.x; Qs[row][j + 1] = v0.y; Qs[row][j + 2] = v0.z; Qs[row][j + 3] = v0.w;
        Qs[row][j + 4] = v1.x; Qs[row][j + 5] = v1.y; Qs[row][j + 6] = v1.z; Qs[row][j + 7] = v1.w;
        Qs[row][j + 8] = v2.x; Qs[row][j + 9] = v2.y; Qs[row][j +10] = v2.z; Qs[row][j +11] = v2.w;
        Qs[row][j +12] = v3.x; Qs[row][j +13] = v3.y; Qs[row][j +14] = v3.z; Qs[row][j +15] = v3.w;
    }
    if (tid < 128) {
        float2 st = g_stats[(size_t)z * S_ + m0 + tid];
        ms[tid] = st.x; il[tid] = st.y;
    }
    __syncthreads();

    unsigned long long acc2[8][4];
    #pragma unroll
    for (int i = 0; i < 8; i++)
        #pragma unroll
        for (int j = 0; j < 4; j++) acc2[i][j] = 0ULL;

    for (int k0 = 0; k0 < kmax; k0 += 16) {
        if (tid < 128) {   // K tile 16x32 — vector gmem load, scalar smem store
            int row = tid >> 3, j = (tid & 7) * 4;
            float4 v = *(const float4*)(g_proj + (size_t)(bb * S_ + k0 + row) * 128 + a * 64 + 32 + j);
            Ks[row][j] = v.x; Ks[row][j + 1] = v.y; Ks[row][j + 2] = v.z; Ks[row][j + 3] = v.w;
        }
        {   // B tile 16x128 from h (row stride 128 floats = 512B, aligned)
            int bk = tid >> 4, bn = (tid & 15) * 8;
            const float4* bp = (const float4*)(Bm + (size_t)(k0 + bk) * H_ + n0 + bn);
            *(float4*)&Bs[bk][bn]     = bp[0];
            *(float4*)&Bs[bk][bn + 4] = bp[1];
        }
        __syncthreads();

        {   // A-gen: As[kk][m] = P value, 8 m's per thread
            int t = k0 + kkA;
            int mv = mask[bb * S_ + t];
            float av[8];
            #pragma unroll
            for (int i = 0; i < 8; i++) av[i] = 0.0f;
            #pragma unroll
            for (int j = 0; j < 32; j++) {
                float kvj = Ks[kkA][j];
                #pragma unroll
                for (int i = 0; i < 8; i++) av[i] += Qs[mgA + i][j] * kvj;
            }
            float ov[8];
            #pragma unroll
            for (int i = 0; i < 8; i++) {
                int m = mgA + i, s = m0 + m;
                ov[i] = (mv && t <= s) ? __expf(av[i] * SCALE_ - ms[m]) * il[m] : 0.0f;
            }
            // As row stride = 132 floats = 528 B (16B multiple) -> float4 OK
            *(float4*)&As[kkA][mgA]     = make_float4(ov[0], ov[1], ov[2], ov[3]);
            *(float4*)&As[kkA][mgA + 4] = make_float4(ov[4], ov[5], ov[6], ov[7]);
        }
        __syncthreads();

        #pragma unroll
        for (int kk = 0; kk < 16; kk++) {
            const unsigned long long* b64 = (const unsigned long long*)&Bs[kk][tn * 8];
            unsigned long long bb0 = b64[0], bb1 = b64[1], bb2 = b64[2], bb3 = b64[3];
            float4 av0 = *(const float4*)&As[kk][tm * 8];
            float4 av1 = *(const float4*)&As[kk][tm * 8 + 4];
            unsigned long long a2_0 = pk2(av0.x), a2_1 = pk2(av0.y), a2_2 = pk2(av0.z), a2_3 = pk2(av0.w);
            unsigned long long a2_4 = pk2(av1.x), a2_5 = pk2(av1.y), a2_6 = pk2(av1.z), a2_7 = pk2(av1.w);
            fma2(acc2[0][0], a2_0, bb0); fma2(acc2[0][1], a2_0, bb1); fma2(acc2[0][2], a2_0, bb2); fma2(acc2[0][3], a2_0, bb3);
            fma2(acc2[1][0], a2_1, bb0); fma2(acc2[1][1], a2_1, bb1); fma2(acc2[1][2], a2_1, bb2); fma2(acc2[1][3], a2_1, bb3);
            fma2(acc2[2][0], a2_2, bb0); fma2(acc2[2][1], a2_2, bb1); fma2(acc2[2][2], a2_2, bb2); fma2(acc2[2][3], a2_2, bb3);
            fma2(acc2[3][0], a2_3, bb0); fma2(acc2[3][1], a2_3, bb1); fma2(acc2[3][2], a2_3, bb2); fma2(acc2[3][3], a2_3, bb3);
            fma2(acc2[4][0], a2_4, bb0); fma2(acc2[4][1], a2_4, bb1); fma2(acc2[4][2], a2_4, bb2); fma2(acc2[4][3], a2_4, bb3);
            fma2(acc2[5][0], a2_5, bb0); fma2(acc2[5][1], a2_5, bb1); fma2(acc2[5][2], a2_5, bb2); fma2(acc2[5][3], a2_5, bb3);
            fma2(acc2[6][0], a2_6, bb0); fma2(acc2[6][1], a2_6, bb1); fma2(acc2[6][2], a2_6, bb2); fma2(acc2[6][3], a2_6, bb3);
            fma2(acc2[7][0], a2_7, bb0); fma2(acc2[7][1], a2_7, bb1); fma2(acc2[7][2], a2_7, bb2); fma2(acc2[7][3], a2_7, bb3);
        }
        __syncthreads();
    }

    #pragma unroll
    for (int i = 0; i < 8; i++) {
        int row = m0 + tm * 8 + i;
        float c0, c1, c2, c3, c4, c5, c6, c7;
        upk(acc2[i][0], c0, c1); upk(acc2[i][1], c2, c3);
        upk(acc2[i][2], c4, c5); upk(acc2[i][3], c6, c7);
        *(float4*)(C + (size_t)row * S_ + n0 + tn * 8)     = make_float4(c0, c1, c2, c3);
        *(float4*)(C + (size_t)row * S_ + n0 + tn * 8 + 4) = make_float4(c4, c5, c6, c7);
    }
}

// ---------------- K5: logits = Y @ W2^T + b2 ; d = argmax per digit ----------
__global__ void __launch_bounds__(256) head_kernel(int which,
                                                   const float* __restrict__ W2,
                                                   const float* __restrict__ b2,
                                                   float* __restrict__ dout,
                                                   float* __restrict__ lout) {
    const float* Y = g_Y + (size_t)which * BS_ * 128;
    int r0 = blockIdx.x * 16;
    int half = blockIdx.y;
    int cbase = half * 50;
    __shared__ float ys[16][128];
    __shared__ float ws[50][128];
    __shared__ float ls[16][52];
    int tid = threadIdx.x;
    {
        int row = tid >> 4, kq = (tid & 15) * 8;
        const float4* p = (const float4*)(Y + (size_t)(r0 + row) * 128 + kq);
        *(float4*)&ys[row][kq]     = p[0];
        *(float4*)&ys[row][kq + 4] = p[1];
    }
    for (int i4 = tid; i4 < 1600; i4 += 256) {
        int c = i4 >> 5, k4 = (i4 & 31) * 4;
        *(float4*)&ws[c][k4] = *(const float4*)(W2 + (size_t)(cbase + c) * 128 + k4);
    }
    __syncthreads();

    for (int idx = tid; idx < 800; idx += 256) {
        int row = idx / 50, c = idx - row * 50;
        float acc = b2[cbase + c];
        const float4* yp = (const float4*)ys[row];
        const float4* wp = (const float4*)ws[c];
        #pragma unroll
        for (int k = 0; k < 32; k++) {
            float4 yv = yp[k], wv = wp[k];
            acc += yv.x * wv.x + yv.y * wv.y + yv.z * wv.z + yv.w * wv.w;
        }
        ls[row][c] = acc;
        lout[(size_t)(r0 + row) * 100 + cbase + c] = acc;
    }
    __syncthreads();

    if (tid < 80) {
        int row = tid / 5, dg = tid - row * 5;
        float best = ls[row][dg * 10];
        int bi = 0;
        #pragma unroll
        for (int k = 1; k < 10; k++) {
            float v = ls[row][dg * 10 + k];
            if (v > best) { best = v; bi = k; }
        }
        dout[(size_t)(r0 + row) * 10 + half * 5 + dg] = (float)bi;
    }
}

// ---------------- launch (kernel launches ONLY — graph-capture safe) ---------
extern "C" void kernel_launch(void* const* d_in, const int* in_sizes, int n_in,
                              void* d_out, int out_size) {
    const float* h    = (const float*)d_in[0];
    const int*   mask = (const int*)  d_in[1];
    const float* Wq_a = (const float*)d_in[2];
    const float* Wk_a = (const float*)d_in[3];
    const float* Wq_b = (const float*)d_in[4];
    const float* Wk_b = (const float*)d_in[5];
    const float* W1_a = (const float*)d_in[6];
    const float* b1_a = (const float*)d_in[7];
    const float* W2_a = (const float*)d_in[8];
    const float* b2_a = (const float*)d_in[9];
    const float* W1_b = (const float*)d_in[10];
    const float* b1_b = (const float*)d_in[11];
    const float* W2_b = (const float*)d_in[12];
    const float* b2_b = (const float*)d_in[13];
    float* out = (float*)d_out;

    // K0: pack W for projections
    pack_w<<<(128 * H_ + 255) / 256, 256>>>(Wq_a, Wk_a, Wq_b, Wk_b);
    // K1: Q/K projections for both attentions (fused into one GEMM)
    gemm_h128<<<BS_ / 64, 256>>>(h, nullptr, nullptr, 0);
    // K2: per-row softmax stats
    softmax_stats<<<dim3(S_ / 32, 8), 256>>>(mask);
    // K3: attn @ h (P regenerated on the fly, causal-truncated)
    gemm_pav2<<<dim3(16, 16, 8), 256>>>(h, mask);
    // K4: MLP hidden + gelu
    gemm_h128<<<BS_ / 64, 256>>>(nullptr, W1_a, b1_a, 1);
    gemm_h128<<<BS_ / 64, 256>>>(nullptr, W1_b, b1_b, 2);
    // K5: logits + STE argmax.  Output layout: [d_a | d_b | logits_a | logits_b]
    head_kernel<<<dim3(512, 2), 256>>>(0, W2_a, b2_a, out,         out + 163840);
    head_kernel<<<dim3(512, 2), 256>>>(1, W2_b, b2_b, out + 81920, out + 983040);
}

// round 7
// speedup vs baseline: 1.2516x; 1.2516x over previous
#include <cuda_runtime.h>
#include <cstdint>
#include <math.h>

#define S_  2048
#define B_  4
#define H_  2048
#define BS_ 8192
#define NEGV (-1e9f)
#define SCALE_ 0.17677669529663687f

typedef unsigned long long ull;

// ---------------- scratch (static __device__, no allocations) ----------------
__device__ __align__(128) float  g_Wcat[128 * H_];                 // 1 MB
__device__ __align__(128) float  g_proj[(size_t)BS_ * 128];        // 4 MB  [Qa|Ka|Qb|Kb]
__device__ __align__(128) float2 g_stats[(size_t)8 * S_];          // 128 KB {max, 1/sum}
__device__ __align__(128) float  g_AO[(size_t)8 * S_ * S_];        // 134 MB
__device__ __align__(128) float  g_Y [(size_t)2 * BS_ * 128];      // 8 MB

// ---------------- f32x2 packed FMA helpers (Blackwell FFMA2) ----------------
__device__ __forceinline__ ull pk(float lo, float hi) {
    ull r; asm("mov.b64 %0, {%1, %2};" : "=l"(r) : "f"(lo), "f"(hi)); return r;
}
__device__ __forceinline__ ull pk2(float v) {
    ull r; asm("mov.b64 %0, {%1, %1};" : "=l"(r) : "f"(v)); return r;
}
__device__ __forceinline__ void upk(ull v, float &lo, float &hi) {
    asm("mov.b64 {%0, %1}, %2;" : "=f"(lo), "=f"(hi) : "l"(v));
}
__device__ __forceinline__ void fma2(ull &d, ull a, ull b) {
    asm("fma.rn.f32x2 %0, %1, %2, %0;" : "+l"(d) : "l"(a), "l"(b));
}

__device__ __forceinline__ float gelu_exact(float x) {
    return 0.5f * x * (1.0f + erff(x * 0.7071067811865476f));
}

// ---------------- K0: pack the 4 attention projection weights ----------------
__global__ void pack_w(const float* __restrict__ qa, const float* __restrict__ ka,
                       const float* __restrict__ qb, const float* __restrict__ kb) {
    int i = blockIdx.x * blockDim.x + threadIdx.x;
    if (i >= 128 * H_) return;
    int c = i >> 11;
    int k = i & 2047;
    const float* src = (c < 32) ? qa + (size_t)c * H_
                     : (c < 64) ? ka + (size_t)(c - 32) * H_
                     : (c < 96) ? qb + (size_t)(c - 64) * H_
                                : kb + (size_t)(c - 96) * H_;
    g_Wcat[i] = src[k];
}

// ---------------- K1/K4: Out[8192,128] = act(X[8192,2048] @ W[128,2048]^T + b)
__global__ void __launch_bounds__(256) gemm_h128(const float* __restrict__ Xext,
                                                 const float* __restrict__ Wext,
                                                 const float* __restrict__ bias,
                                                 int mode) {
    const float* X = (mode == 0) ? Xext : (mode == 1) ? g_AO : (g_AO + (size_t)4 * S_ * S_);
    const float* W = (mode == 0) ? g_Wcat : Wext;
    float* Out     = (mode == 0) ? g_proj : (mode == 1) ? g_Y : (g_Y + (size_t)BS_ * 128);
    int act = (mode != 0);

    __shared__ float xsT[32][66];    // [k][m] -> m-pairs contiguous for LDS.64
    __shared__ float ws[128][33];
    int tid = threadIdx.x;
    int r0  = blockIdx.x * 64;
    int rg  = tid >> 5;     // warp id -> rows rg*8 .. rg*8+7
    int cg  = tid & 31;     // cols cg + 32*j

    ull acc2[4][4];
    #pragma unroll
    for (int i = 0; i < 4; i++)
        #pragma unroll
        for (int j = 0; j < 4; j++) acc2[i][j] = 0ULL;

    for (int k0 = 0; k0 < H_; k0 += 32) {
        {   // X tile 64x32 -> transposed xsT[k][m]
            int row = tid >> 2, kq = (tid & 3) * 8;
            const float4* p = (const float4*)(X + (size_t)(r0 + row) * H_ + k0 + kq);
            float4 v0 = p[0], v1 = p[1];
            xsT[kq + 0][row] = v0.x; xsT[kq + 1][row] = v0.y;
            xsT[kq + 2][row] = v0.z; xsT[kq + 3][row] = v0.w;
            xsT[kq + 4][row] = v1.x; xsT[kq + 5][row] = v1.y;
            xsT[kq + 6][row] = v1.z; xsT[kq + 7][row] = v1.w;
        }
        {   // W tile 128x32
            int c = tid >> 1, kq = (tid & 1) * 16;
            const float4* p = (const float4*)(W + (size_t)c * H_ + k0 + kq);
            float4 v0 = p[0], v1 = p[1], v2 = p[2], v3 = p[3];
            ws[c][kq + 0] = v0.x; ws[c][kq + 1] = v0.y; ws[c][kq + 2] = v0.z; ws[c][kq + 3] = v0.w;
            ws[c][kq + 4] = v1.x; ws[c][kq + 5] = v1.y; ws[c][kq + 6] = v1.z; ws[c][kq + 7] = v1.w;
            ws[c][kq + 8] = v2.x; ws[c][kq + 9] = v2.y; ws[c][kq +10] = v2.z; ws[c][kq +11] = v2.w;
            ws[c][kq +12] = v3.x; ws[c][kq +13] = v3.y; ws[c][kq +14] = v3.z; ws[c][kq +15] = v3.w;
        }
        __syncthreads();
        #pragma unroll
        for (int kk = 0; kk < 32; kk++) {
            ull a0 = *(const ull*)&xsT[kk][rg * 8 + 0];
            ull a1 = *(const ull*)&xsT[kk][rg * 8 + 2];
            ull a2 = *(const ull*)&xsT[kk][rg * 8 + 4];
            ull a3 = *(const ull*)&xsT[kk][rg * 8 + 6];
            ull b0 = pk2(ws[cg      ][kk]);
            ull b1 = pk2(ws[cg + 32 ][kk]);
            ull b2 = pk2(ws[cg + 64 ][kk]);
            ull b3 = pk2(ws[cg + 96 ][kk]);
            fma2(acc2[0][0], a0, b0); fma2(acc2[0][1], a0, b1); fma2(acc2[0][2], a0, b2); fma2(acc2[0][3], a0, b3);
            fma2(acc2[1][0], a1, b0); fma2(acc2[1][1], a1, b1); fma2(acc2[1][2], a1, b2); fma2(acc2[1][3], a1, b3);
            fma2(acc2[2][0], a2, b0); fma2(acc2[2][1], a2, b1); fma2(acc2[2][2], a2, b2); fma2(acc2[2][3], a2, b3);
            fma2(acc2[3][0], a3, b0); fma2(acc2[3][1], a3, b1); fma2(acc2[3][2], a3, b2); fma2(acc2[3][3], a3, b3);
        }
        __syncthreads();
    }

    #pragma unroll
    for (int i2 = 0; i2 < 4; i2++) {
        #pragma unroll
        for (int j = 0; j < 4; j++) {
            float lo, hi; upk(acc2[i2][j], lo, hi);
            int col  = cg + 32 * j;
            int row0 = r0 + rg * 8 + 2 * i2;
            float bsv = bias ? bias[col] : 0.0f;
            float v0 = lo + bsv, v1 = hi + bsv;
            if (act) { v0 = gelu_exact(v0); v1 = gelu_exact(v1); }
            Out[(size_t)row0 * 128 + col]       = v0;
            Out[(size_t)(row0 + 1) * 128 + col] = v1;
        }
    }
}

// ---------------- K2: per-row softmax stats (max, 1/sumexp) ------------------
__global__ void __launch_bounds__(256) softmax_stats(const int* __restrict__ mask) {
    int z = blockIdx.y, a = z >> 2, bb = z & 3;
    int s0 = blockIdx.x * 32;
    int tid = threadIdx.x, lane = tid & 31, w = tid >> 5;

    __shared__ float Qs[32][33];
    __shared__ float Ks[32][33];
    {
        int row = tid >> 3, j = (tid & 7) * 4;
        float4 v = *(const float4*)(g_proj + (size_t)(bb * S_ + s0 + row) * 128 + a * 64 + j);
        Qs[row][j] = v.x; Qs[row][j + 1] = v.y; Qs[row][j + 2] = v.z; Qs[row][j + 3] = v.w;
    }

    int tmax = s0 + 31;
    float mreg[4] = {NEGV, NEGV, NEGV, NEGV};

    for (int t0 = 0; t0 <= tmax; t0 += 32) {
        __syncthreads();
        {   int row = tid >> 3, j = (tid & 7) * 4;
            float4 v = *(const float4*)(g_proj + (size_t)(bb * S_ + t0 + row) * 128 + a * 64 + 32 + j);
            Ks[row][j] = v.x; Ks[row][j + 1] = v.y; Ks[row][j + 2] = v.z; Ks[row][j + 3] = v.w;
        }
        __syncthreads();
        int t = t0 + lane;
        int mv = mask[bb * S_ + t];
        #pragma unroll
        for (int rr = 0; rr < 4; rr++) {
            int sl = w * 4 + rr, s = s0 + sl;
            float dot = 0.0f;
            #pragma unroll
            for (int j = 0; j < 32; j++) dot += Qs[sl][j] * Ks[lane][j];
            float x = (t <= s && mv) ? dot * SCALE_ : NEGV;
            mreg[rr] = fmaxf(mreg[rr], x);
        }
    }
    float mfin[4];
    #pragma unroll
    for (int rr = 0; rr < 4; rr++) {
        float m = mreg[rr];
        #pragma unroll
        for (int off = 16; off > 0; off >>= 1)
            m = fmaxf(m, __shfl_xor_sync(0xffffffffu, m, off));
        mfin[rr] = m;
    }

    float lreg[4] = {0.f, 0.f, 0.f, 0.f};
    for (int t0 = 0; t0 <= tmax; t0 += 32) {
        __syncthreads();
        {   int row = tid >> 3, j = (tid & 7) * 4;
            float4 v = *(const float4*)(g_proj + (size_t)(bb * S_ + t0 + row) * 128 + a * 64 + 32 + j);
            Ks[row][j] = v.x; Ks[row][j + 1] = v.y; Ks[row][j + 2] = v.z; Ks[row][j + 3] = v.w;
        }
        __syncthreads();
        int t = t0 + lane;
        int mv = mask[bb * S_ + t];
        #pragma unroll
        for (int rr = 0; rr < 4; rr++) {
            int sl = w * 4 + rr, s = s0 + sl;
            float dot = 0.0f;
            #pragma unroll
            for (int j = 0; j < 32; j++) dot += Qs[sl][j] * Ks[lane][j];
            float x = (t <= s && mv) ? dot * SCALE_ : NEGV;
            lreg[rr] += __expf(x - mfin[rr]);
        }
    }
    #pragma unroll
    for (int rr = 0; rr < 4; rr++) {
        float l = lreg[rr];
        #pragma unroll
        for (int off = 16; off > 0; off >>= 1)
            l += __shfl_xor_sync(0xffffffffu, l, off);
        if (lane == 0) {
            int s = s0 + w * 4 + rr;
            g_stats[(size_t)z * S_ + s] = make_float2(mfin[rr], 1.0f / l);
        }
    }
}

// ---------------- K3: g_AO = softmax(QK^T) @ h, P regenerated on the fly -----
// 128x128 tile, KC=16, double-buffered K/B, FFMA2 A-gen.
// NOTE: no min-blocks clause — forcing 2 CTAs/SM spills the 64 accumulator
// regs (138+ live) and made the kernel catastrophically slow (round 5/6).
__global__ void __launch_bounds__(256) gemm_pav2(const float* __restrict__ hbase,
                                                 const int* __restrict__ mask) {
    int bxn = blockIdx.x, bym = 15 - blockIdx.y, z = blockIdx.z;  // heavy tiles first
    int a = z >> 2, bb = z & 3;
    const float* Bm = hbase + (size_t)bb * S_ * H_;
    float* C = g_AO + (size_t)z * S_ * S_;
    int m0 = bym * 128, n0 = bxn * 128;
    int kmax = m0 + 128;   // P[s][t]==0 exactly for t>s

    __shared__ float QsT[32][132];     // [j][m] -> m-pairs contiguous
    __shared__ float Ks[2][16][33];
    __shared__ float As[16][132];
    __shared__ float Bs[2][16][128];
    __shared__ float ms[128];
    __shared__ float il[128];

    int tid = threadIdx.x;
    int tm = tid >> 4, tn = tid & 15;
    int kkA = tid & 15, mgA = (tid >> 4) * 8;
    int krow = tid >> 3, kj = (tid & 7) * 4;   // Ks fill (tid<128)
    int brow = tid >> 4, bn = (tid & 15) * 8;  // Bs fill

    {   // Q rows m0..m0+127, transposed into QsT[j][m]
        int row = tid >> 1, j0 = (tid & 1) * 16;
        const float4* p = (const float4*)(g_proj + (size_t)(bb * S_ + m0 + row) * 128 + a * 64 + j0);
        float4 v0 = p[0], v1 = p[1], v2 = p[2], v3 = p[3];
        QsT[j0 + 0][row] = v0.x; QsT[j0 + 1][row] = v0.y; QsT[j0 + 2][row] = v0.z; QsT[j0 + 3][row] = v0.w;
        QsT[j0 + 4][row] = v1.x; QsT[j0 + 5][row] = v1.y; QsT[j0 + 6][row] = v1.z; QsT[j0 + 7][row] = v1.w;
        QsT[j0 + 8][row] = v2.x; QsT[j0 + 9][row] = v2.y; QsT[j0 +10][row] = v2.z; QsT[j0 +11][row] = v2.w;
        QsT[j0 +12][row] = v3.x; QsT[j0 +13][row] = v3.y; QsT[j0 +14][row] = v3.z; QsT[j0 +15][row] = v3.w;
    }
    if (tid < 128) {
        float2 st = g_stats[(size_t)z * S_ + m0 + tid];
        ms[tid] = st.x; il[tid] = st.y;
    }
    // initial K/B tiles (k0 = 0)
    if (tid < 128) {
        float4 v = *(const float4*)(g_proj + (size_t)(bb * S_ + krow) * 128 + a * 64 + 32 + kj);
        Ks[0][krow][kj] = v.x; Ks[0][krow][kj + 1] = v.y; Ks[0][krow][kj + 2] = v.z; Ks[0][krow][kj + 3] = v.w;
    }
    {
        const float4* bp = (const float4*)(Bm + (size_t)brow * H_ + n0 + bn);
        *(float4*)&Bs[0][brow][bn]     = bp[0];
        *(float4*)&Bs[0][brow][bn + 4] = bp[1];
    }
    __syncthreads();

    ull acc2[8][4];
    #pragma unroll
    for (int i = 0; i < 8; i++)
        #pragma unroll
        for (int j = 0; j < 4; j++) acc2[i][j] = 0ULL;

    for (int k0 = 0; k0 < kmax; k0 += 16) {
        int buf = (k0 >> 4) & 1;
        bool hasNext = (k0 + 16) < kmax;
        float4 nk, nb0, nb1;
        if (hasNext) {   // prefetch next tiles into registers
            if (tid < 128)
                nk = *(const float4*)(g_proj + (size_t)(bb * S_ + k0 + 16 + krow) * 128 + a * 64 + 32 + kj);
            const float4* bp = (const float4*)(Bm + (size_t)(k0 + 16 + brow) * H_ + n0 + bn);
            nb0 = bp[0]; nb1 = bp[1];
        }
        {   // A-gen: As[kkA][m] = P, FFMA2 over m-pairs
            int t = k0 + kkA;
            int mv = mask[bb * S_ + t];
            ull av2[4] = {0ULL, 0ULL, 0ULL, 0ULL};
            #pragma unroll
            for (int j = 0; j < 32; j++) {
                ull kv = pk2(Ks[buf][kkA][j]);
                fma2(av2[0], kv, *(const ull*)&QsT[j][mgA + 0]);
                fma2(av2[1], kv, *(const ull*)&QsT[j][mgA + 2]);
                fma2(av2[2], kv, *(const ull*)&QsT[j][mgA + 4]);
                fma2(av2[3], kv, *(const ull*)&QsT[j][mgA + 6]);
            }
            #pragma unroll
            for (int i = 0; i < 4; i++) {
                float lo, hi; upk(av2[i], lo, hi);
                int mA = mgA + 2 * i;
                int sA = m0 + mA;
                float o0 = (mv && t <= sA)     ? __expf(lo * SCALE_ - ms[mA])     * il[mA]     : 0.0f;
                float o1 = (mv && t <= sA + 1) ? __expf(hi * SCALE_ - ms[mA + 1]) * il[mA + 1] : 0.0f;
                *(ull*)&As[kkA][mA] = pk(o0, o1);
            }
        }
        __syncthreads();
        #pragma unroll
        for (int kk = 0; kk < 16; kk++) {
            const ull* b64 = (const ull*)&Bs[buf][kk][tn * 8];
            ull bb0 = b64[0], bb1 = b64[1], bb2 = b64[2], bb3 = b64[3];
            float4 av0 = *(const float4*)&As[kk][tm * 8];
            float4 av1 = *(const float4*)&As[kk][tm * 8 + 4];
            ull a2_0 = pk2(av0.x), a2_1 = pk2(av0.y), a2_2 = pk2(av0.z), a2_3 = pk2(av0.w);
            ull a2_4 = pk2(av1.x), a2_5 = pk2(av1.y), a2_6 = pk2(av1.z), a2_7 = pk2(av1.w);
            fma2(acc2[0][0], a2_0, bb0); fma2(acc2[0][1], a2_0, bb1); fma2(acc2[0][2], a2_0, bb2); fma2(acc2[0][3], a2_0, bb3);
            fma2(acc2[1][0], a2_1, bb0); fma2(acc2[1][1], a2_1, bb1); fma2(acc2[1][2], a2_1, bb2); fma2(acc2[1][3], a2_1, bb3);
            fma2(acc2[2][0], a2_2, bb0); fma2(acc2[2][1], a2_2, bb1); fma2(acc2[2][2], a2_2, bb2); fma2(acc2[2][3], a2_2, bb3);
            fma2(acc2[3][0], a2_3, bb0); fma2(acc2[3][1], a2_3, bb1); fma2(acc2[3][2], a2_3, bb2); fma2(acc2[3][3], a2_3, bb3);
            fma2(acc2[4][0], a2_4, bb0); fma2(acc2[4][1], a2_4, bb1); fma2(acc2[4][2], a2_4, bb2); fma2(acc2[4][3], a2_4, bb3);
            fma2(acc2[5][0], a2_5, bb0); fma2(acc2[5][1], a2_5, bb1); fma2(acc2[5][2], a2_5, bb2); fma2(acc2[5][3], a2_5, bb3);
            fma2(acc2[6][0], a2_6, bb0); fma2(acc2[6][1], a2_6, bb1); fma2(acc2[6][2], a2_6, bb2); fma2(acc2[6][3], a2_6, bb3);
            fma2(acc2[7][0], a2_7, bb0); fma2(acc2[7][1], a2_7, bb1); fma2(acc2[7][2], a2_7, bb2); fma2(acc2[7][3], a2_7, bb3);
        }
        if (hasNext) {   // commit prefetched tiles to the other buffer
            int nbuf = buf ^ 1;
            if (tid < 128) {
                Ks[nbuf][krow][kj]     = nk.x; Ks[nbuf][krow][kj + 1] = nk.y;
                Ks[nbuf][krow][kj + 2] = nk.z; Ks[nbuf][krow][kj + 3] = nk.w;
            }
            *(float4*)&Bs[nbuf][brow][bn]     = nb0;
            *(float4*)&Bs[nbuf][brow][bn + 4] = nb1;
        }
        __syncthreads();
    }

    #pragma unroll
    for (int i = 0; i < 8; i++) {
        int row = m0 + tm * 8 + i;
        float c0, c1, c2, c3, c4, c5, c6, c7;
        upk(acc2[i][0], c0, c1); upk(acc2[i][1], c2, c3);
        upk(acc2[i][2], c4, c5); upk(acc2[i][3], c6, c7);
        *(float4*)(C + (size_t)row * S_ + n0 + tn * 8)     = make_float4(c0, c1, c2, c3);
        *(float4*)(C + (size_t)row * S_ + n0 + tn * 8 + 4) = make_float4(c4, c5, c6, c7);
    }
}

// ---------------- K5: logits = Y @ W2^T + b2 ; d = argmax per digit ----------
__global__ void __launch_bounds__(256) head_kernel(int which,
                                                   const float* __restrict__ W2,
                                                   const float* __restrict__ b2,
                                                   float* __restrict__ dout,
                                                   float* __restrict__ lout) {
    const float* Y = g_Y + (size_t)which * BS_ * 128;
    int r0 = blockIdx.x * 16;
    int half = blockIdx.y;
    int cbase = half * 50;
    __shared__ float ys[16][128];
    __shared__ float ws[50][128];
    __shared__ float ls[16][52];
    int tid = threadIdx.x;
    {
        int row = tid >> 4, kq = (tid & 15) * 8;
        const float4* p = (const float4*)(Y + (size_t)(r0 + row) * 128 + kq);
        *(float4*)&ys[row][kq]     = p[0];
        *(float4*)&ys[row][kq + 4] = p[1];
    }
    for (int i4 = tid; i4 < 1600; i4 += 256) {
        int c = i4 >> 5, k4 = (i4 & 31) * 4;
        *(float4*)&ws[c][k4] = *(const float4*)(W2 + (size_t)(cbase + c) * 128 + k4);
    }
    __syncthreads();

    for (int idx = tid; idx < 800; idx += 256) {
        int row = idx / 50, c = idx - row * 50;
        float acc = b2[cbase + c];
        const float4* yp = (const float4*)ys[row];
        const float4* wp = (const float4*)ws[c];
        #pragma unroll
        for (int k = 0; k < 32; k++) {
            float4 yv = yp[k], wv = wp[k];
            acc += yv.x * wv.x + yv.y * wv.y + yv.z * wv.z + yv.w * wv.w;
        }
        ls[row][c] = acc;
        lout[(size_t)(r0 + row) * 100 + cbase + c] = acc;
    }
    __syncthreads();

    if (tid < 80) {
        int row = tid / 5, dg = tid - row * 5;
        float best = ls[row][dg * 10];
        int bi = 0;
        #pragma unroll
        for (int k = 1; k < 10; k++) {
            float v = ls[row][dg * 10 + k];
            if (v > best) { best = v; bi = k; }
        }
        dout[(size_t)(r0 + row) * 10 + half * 5 + dg] = (float)bi;
    }
}

// ---------------- launch (kernel launches ONLY — graph-capture safe) ---------
extern "C" void kernel_launch(void* const* d_in, const int* in_sizes, int n_in,
                              void* d_out, int out_size) {
    const float* h    = (const float*)d_in[0];
    const int*   mask = (const int*)  d_in[1];
    const float* Wq_a = (const float*)d_in[2];
    const float* Wk_a = (const float*)d_in[3];
    const float* Wq_b = (const float*)d_in[4];
    const float* Wk_b = (const float*)d_in[5];
    const float* W1_a = (const float*)d_in[6];
    const float* b1_a = (const float*)d_in[7];
    const float* W2_a = (const float*)d_in[8];
    const float* b2_a = (const float*)d_in[9];
    const float* W1_b = (const float*)d_in[10];
    const float* b1_b = (const float*)d_in[11];
    const float* W2_b = (const float*)d_in[12];
    const float* b2_b = (const float*)d_in[13];
    float* out = (float*)d_out;

    pack_w<<<(128 * H_ + 255) / 256, 256>>>(Wq_a, Wk_a, Wq_b, Wk_b);
    gemm_h128<<<BS_ / 64, 256>>>(h, nullptr, nullptr, 0);
    softmax_stats<<<dim3(S_ / 32, 8), 256>>>(mask);
    gemm_pav2<<<dim3(16, 16, 8), 256>>>(h, mask);
    gemm_h128<<<BS_ / 64, 256>>>(nullptr, W1_a, b1_a, 1);
    gemm_h128<<<BS_ / 64, 256>>>(nullptr, W1_b, b1_b, 2);
    head_kernel<<<dim3(512, 2), 256>>>(0, W2_a, b2_a, out,         out + 163840);
    head_kernel<<<dim3(512, 2), 256>>>(1, W2_b, b2_b, out + 81920, out + 983040);
}

// round 8
// speedup vs baseline: 3.4961x; 2.7934x over previous
#include <cuda_runtime.h>
#include <cstdint>
#include <math.h>

#define S_  2048
#define B_  4
#define H_  2048
#define BS_ 8192
#define NEGV (-1e9f)
#define SCALE_ 0.17677669529663687f

typedef unsigned long long ull;

// ---------------- scratch (static __device__, no allocations) ----------------
__device__ __align__(128) float  g_Wcat[128 * H_];                 // 1 MB
__device__ __align__(128) float  g_proj[(size_t)BS_ * 128];        // 4 MB  [Qa|Ka|Qb|Kb]
__device__ __align__(128) float2 g_stats[(size_t)8 * S_];          // 128 KB {max, 1/sum}
__device__ __align__(128) float  g_hW1[(size_t)2 * BS_ * 128];     // 8 MB  h @ W1_{a,b}^T
__device__ __align__(128) float  g_Y [(size_t)2 * BS_ * 128];      // 8 MB  MLP hidden (gelu'd)

// ---------------- f32x2 packed FMA helpers (Blackwell FFMA2) ----------------
__device__ __forceinline__ ull pk(float lo, float hi) {
    ull r; asm("mov.b64 %0, {%1, %2};" : "=l"(r) : "f"(lo), "f"(hi)); return r;
}
__device__ __forceinline__ ull pk2(float v) {
    ull r; asm("mov.b64 %0, {%1, %1};" : "=l"(r) : "f"(v)); return r;
}
__device__ __forceinline__ void upk(ull v, float &lo, float &hi) {
    asm("mov.b64 {%0, %1}, %2;" : "=f"(lo), "=f"(hi) : "l"(v));
}
__device__ __forceinline__ void fma2(ull &d, ull a, ull b) {
    asm("fma.rn.f32x2 %0, %1, %2, %0;" : "+l"(d) : "l"(a), "l"(b));
}

__device__ __forceinline__ float gelu_exact(float x) {
    return 0.5f * x * (1.0f + erff(x * 0.7071067811865476f));
}

// ---------------- K0: pack the 4 attention projection weights ----------------
__global__ void pack_w(const float* __restrict__ qa, const float* __restrict__ ka,
                       const float* __restrict__ qb, const float* __restrict__ kb) {
    int i = blockIdx.x * blockDim.x + threadIdx.x;
    if (i >= 128 * H_) return;
    int c = i >> 11;
    int k = i & 2047;
    const float* src = (c < 32) ? qa + (size_t)c * H_
                     : (c < 64) ? ka + (size_t)(c - 32) * H_
                     : (c < 96) ? qb + (size_t)(c - 64) * H_
                                : kb + (size_t)(c - 96) * H_;
    g_Wcat[i] = src[k];
}

// ---------------- K1: fused projections. grid (128, 3).
// y=0: proj = h @ Wcat^T ; y=1: hW1_a = h @ W1_a^T ; y=2: hW1_b = h @ W1_b^T
__global__ void __launch_bounds__(256) gemm_h128(const float* __restrict__ h,
                                                 const float* __restrict__ W1a,
                                                 const float* __restrict__ W1b) {
    int sel = blockIdx.y;
    const float* X = h;
    const float* W = (sel == 0) ? g_Wcat : (sel == 1) ? W1a : W1b;
    float* Out     = (sel == 0) ? g_proj : g_hW1 + (size_t)(sel - 1) * BS_ * 128;

    __shared__ float xsT[32][66];    // [k][m] -> m-pairs contiguous for LDS.64
    __shared__ float ws[128][33];
    int tid = threadIdx.x;
    int r0  = blockIdx.x * 64;
    int rg  = tid >> 5;     // warp id -> rows rg*8 .. rg*8+7
    int cg  = tid & 31;     // cols cg + 32*j

    ull acc2[4][4];
    #pragma unroll
    for (int i = 0; i < 4; i++)
        #pragma unroll
        for (int j = 0; j < 4; j++) acc2[i][j] = 0ULL;

    for (int k0 = 0; k0 < H_; k0 += 32) {
        {   // X tile 64x32 -> transposed xsT[k][m]
            int row = tid >> 2, kq = (tid & 3) * 8;
            const float4* p = (const float4*)(X + (size_t)(r0 + row) * H_ + k0 + kq);
            float4 v0 = p[0], v1 = p[1];
            xsT[kq + 0][row] = v0.x; xsT[kq + 1][row] = v0.y;
            xsT[kq + 2][row] = v0.z; xsT[kq + 3][row] = v0.w;
            xsT[kq + 4][row] = v1.x; xsT[kq + 5][row] = v1.y;
            xsT[kq + 6][row] = v1.z; xsT[kq + 7][row] = v1.w;
        }
        {   // W tile 128x32
            int c = tid >> 1, kq = (tid & 1) * 16;
            const float4* p = (const float4*)(W + (size_t)c * H_ + k0 + kq);
            float4 v0 = p[0], v1 = p[1], v2 = p[2], v3 = p[3];
            ws[c][kq + 0] = v0.x; ws[c][kq + 1] = v0.y; ws[c][kq + 2] = v0.z; ws[c][kq + 3] = v0.w;
            ws[c][kq + 4] = v1.x; ws[c][kq + 5] = v1.y; ws[c][kq + 6] = v1.z; ws[c][kq + 7] = v1.w;
            ws[c][kq + 8] = v2.x; ws[c][kq + 9] = v2.y; ws[c][kq +10] = v2.z; ws[c][kq +11] = v2.w;
            ws[c][kq +12] = v3.x; ws[c][kq +13] = v3.y; ws[c][kq +14] = v3.z; ws[c][kq +15] = v3.w;
        }
        __syncthreads();
        #pragma unroll
        for (int kk = 0; kk < 32; kk++) {
            ull a0 = *(const ull*)&xsT[kk][rg * 8 + 0];
            ull a1 = *(const ull*)&xsT[kk][rg * 8 + 2];
            ull a2 = *(const ull*)&xsT[kk][rg * 8 + 4];
            ull a3 = *(const ull*)&xsT[kk][rg * 8 + 6];
            ull b0 = pk2(ws[cg      ][kk]);
            ull b1 = pk2(ws[cg + 32 ][kk]);
            ull b2 = pk2(ws[cg + 64 ][kk]);
            ull b3 = pk2(ws[cg + 96 ][kk]);
            fma2(acc2[0][0], a0, b0); fma2(acc2[0][1], a0, b1); fma2(acc2[0][2], a0, b2); fma2(acc2[0][3], a0, b3);
            fma2(acc2[1][0], a1, b0); fma2(acc2[1][1], a1, b1); fma2(acc2[1][2], a1, b2); fma2(acc2[1][3], a1, b3);
            fma2(acc2[2][0], a2, b0); fma2(acc2[2][1], a2, b1); fma2(acc2[2][2], a2, b2); fma2(acc2[2][3], a2, b3);
            fma2(acc2[3][0], a3, b0); fma2(acc2[3][1], a3, b1); fma2(acc2[3][2], a3, b2); fma2(acc2[3][3], a3, b3);
        }
        __syncthreads();
    }

    #pragma unroll
    for (int i2 = 0; i2 < 4; i2++) {
        #pragma unroll
        for (int j = 0; j < 4; j++) {
            float lo, hi; upk(acc2[i2][j], lo, hi);
            int col  = cg + 32 * j;
            int row0 = r0 + rg * 8 + 2 * i2;
            Out[(size_t)row0 * 128 + col]       = lo;
            Out[(size_t)(row0 + 1) * 128 + col] = hi;
        }
    }
}

// ---------------- K2: per-row softmax stats (max, 1/sumexp) ------------------
__global__ void __launch_bounds__(256) softmax_stats(const int* __restrict__ mask) {
    int z = blockIdx.y, a = z >> 2, bb = z & 3;
    int s0 = blockIdx.x * 32;
    int tid = threadIdx.x, lane = tid & 31, w = tid >> 5;

    __shared__ float Qs[32][33];
    __shared__ float Ks[32][33];
    {
        int row = tid >> 3, j = (tid & 7) * 4;
        float4 v = *(const float4*)(g_proj + (size_t)(bb * S_ + s0 + row) * 128 + a * 64 + j);
        Qs[row][j] = v.x; Qs[row][j + 1] = v.y; Qs[row][j + 2] = v.z; Qs[row][j + 3] = v.w;
    }

    int tmax = s0 + 31;
    float mreg[4] = {NEGV, NEGV, NEGV, NEGV};

    for (int t0 = 0; t0 <= tmax; t0 += 32) {
        __syncthreads();
        {   int row = tid >> 3, j = (tid & 7) * 4;
            float4 v = *(const float4*)(g_proj + (size_t)(bb * S_ + t0 + row) * 128 + a * 64 + 32 + j);
            Ks[row][j] = v.x; Ks[row][j + 1] = v.y; Ks[row][j + 2] = v.z; Ks[row][j + 3] = v.w;
        }
        __syncthreads();
        int t = t0 + lane;
        int mv = mask[bb * S_ + t];
        #pragma unroll
        for (int rr = 0; rr < 4; rr++) {
            int sl = w * 4 + rr, s = s0 + sl;
            float dot = 0.0f;
            #pragma unroll
            for (int j = 0; j < 32; j++) dot += Qs[sl][j] * Ks[lane][j];
            float x = (t <= s && mv) ? dot * SCALE_ : NEGV;
            mreg[rr] = fmaxf(mreg[rr], x);
        }
    }
    float mfin[4];
    #pragma unroll
    for (int rr = 0; rr < 4; rr++) {
        float m = mreg[rr];
        #pragma unroll
        for (int off = 16; off > 0; off >>= 1)
            m = fmaxf(m, __shfl_xor_sync(0xffffffffu, m, off));
        mfin[rr] = m;
    }

    float lreg[4] = {0.f, 0.f, 0.f, 0.f};
    for (int t0 = 0; t0 <= tmax; t0 += 32) {
        __syncthreads();
        {   int row = tid >> 3, j = (tid & 7) * 4;
            float4 v = *(const float4*)(g_proj + (size_t)(bb * S_ + t0 + row) * 128 + a * 64 + 32 + j);
            Ks[row][j] = v.x; Ks[row][j + 1] = v.y; Ks[row][j + 2] = v.z; Ks[row][j + 3] = v.w;
        }
        __syncthreads();
        int t = t0 + lane;
        int mv = mask[bb * S_ + t];
        #pragma unroll
        for (int rr = 0; rr < 4; rr++) {
            int sl = w * 4 + rr, s = s0 + sl;
            float dot = 0.0f;
            #pragma unroll
            for (int j = 0; j < 32; j++) dot += Qs[sl][j] * Ks[lane][j];
            float x = (t <= s && mv) ? dot * SCALE_ : NEGV;
            lreg[rr] += __expf(x - mfin[rr]);
        }
    }
    #pragma unroll
    for (int rr = 0; rr < 4; rr++) {
        float l = lreg[rr];
        #pragma unroll
        for (int off = 16; off > 0; off >>= 1)
            l += __shfl_xor_sync(0xffffffffu, l, off);
        if (lane == 0) {
            int s = s0 + w * 4 + rr;
            g_stats[(size_t)z * S_ + s] = make_float2(mfin[rr], 1.0f / l);
        }
    }
}

// ---------------- K3: g_Y = gelu( P @ hW1 + b1 ), P regenerated on the fly ---
// grid (16 m-tiles, 8 slabs). 128x128 output, KC=16 double-buffered, causal-trunc.
__global__ void __launch_bounds__(256) gemm_pz(const int* __restrict__ mask,
                                               const float* __restrict__ b1a,
                                               const float* __restrict__ b1b) {
    int bym = 15 - (int)blockIdx.x;      // heavy tiles first
    int z = blockIdx.y;
    int a = z >> 2, bb = z & 3;
    const float* Bm = g_hW1 + (size_t)a * BS_ * 128 + (size_t)bb * S_ * 128;
    float* Yout     = g_Y  + (size_t)a * BS_ * 128 + (size_t)bb * S_ * 128;
    const float* b1 = a ? b1b : b1a;
    int m0 = bym * 128;
    int kmax = m0 + 128;   // P[s][t]==0 exactly for t>s

    __shared__ float QsT[32][132];     // [j][m] -> m-pairs contiguous
    __shared__ float Ks[2][16][33];
    __shared__ float As[16][132];
    __shared__ float Bs[2][16][128];
    __shared__ float ms[128];
    __shared__ float il[128];

    int tid = threadIdx.x;
    int tm = tid >> 4, tn = tid & 15;
    int kkA = tid & 15, mgA = (tid >> 4) * 8;
    int krow = tid >> 3, kj = (tid & 7) * 4;   // Ks fill (tid<128)
    int brow = tid >> 4, bn = (tid & 15) * 8;  // Bs fill

    {   // Q rows m0..m0+127, transposed into QsT[j][m]
        int row = tid >> 1, j0 = (tid & 1) * 16;
        const float4* p = (const float4*)(g_proj + (size_t)(bb * S_ + m0 + row) * 128 + a * 64 + j0);
        float4 v0 = p[0], v1 = p[1], v2 = p[2], v3 = p[3];
        QsT[j0 + 0][row] = v0.x; QsT[j0 + 1][row] = v0.y; QsT[j0 + 2][row] = v0.z; QsT[j0 + 3][row] = v0.w;
        QsT[j0 + 4][row] = v1.x; QsT[j0 + 5][row] = v1.y; QsT[j0 + 6][row] = v1.z; QsT[j0 + 7][row] = v1.w;
        QsT[j0 + 8][row] = v2.x; QsT[j0 + 9][row] = v2.y; QsT[j0 +10][row] = v2.z; QsT[j0 +11][row] = v2.w;
        QsT[j0 +12][row] = v3.x; QsT[j0 +13][row] = v3.y; QsT[j0 +14][row] = v3.z; QsT[j0 +15][row] = v3.w;
    }
    if (tid < 128) {
        float2 st = g_stats[(size_t)z * S_ + m0 + tid];
        ms[tid] = st.x; il[tid] = st.y;
    }
    // initial K/B tiles (k0 = 0)
    if (tid < 128) {
        float4 v = *(const float4*)(g_proj + (size_t)(bb * S_ + krow) * 128 + a * 64 + 32 + kj);
        Ks[0][krow][kj] = v.x; Ks[0][krow][kj + 1] = v.y; Ks[0][krow][kj + 2] = v.z; Ks[0][krow][kj + 3] = v.w;
    }
    {
        const float4* bp = (const float4*)(Bm + (size_t)brow * 128 + bn);
        *(float4*)&Bs[0][brow][bn]     = bp[0];
        *(float4*)&Bs[0][brow][bn + 4] = bp[1];
    }
    __syncthreads();

    ull acc2[8][4];
    #pragma unroll
    for (int i = 0; i < 8; i++)
        #pragma unroll
        for (int j = 0; j < 4; j++) acc2[i][j] = 0ULL;

    for (int k0 = 0; k0 < kmax; k0 += 16) {
        int buf = (k0 >> 4) & 1;
        bool hasNext = (k0 + 16) < kmax;
        float4 nk, nb0, nb1;
        if (hasNext) {   // prefetch next tiles into registers
            if (tid < 128)
                nk = *(const float4*)(g_proj + (size_t)(bb * S_ + k0 + 16 + krow) * 128 + a * 64 + 32 + kj);
            const float4* bp = (const float4*)(Bm + (size_t)(k0 + 16 + brow) * 128 + bn);
            nb0 = bp[0]; nb1 = bp[1];
        }
        {   // A-gen: As[kkA][m] = P, FFMA2 over m-pairs
            int t = k0 + kkA;
            int mv = mask[bb * S_ + t];
            ull av2[4] = {0ULL, 0ULL, 0ULL, 0ULL};
            #pragma unroll
            for (int j = 0; j < 32; j++) {
                ull kv = pk2(Ks[buf][kkA][j]);
                fma2(av2[0], kv, *(const ull*)&QsT[j][mgA + 0]);
                fma2(av2[1], kv, *(const ull*)&QsT[j][mgA + 2]);
                fma2(av2[2], kv, *(const ull*)&QsT[j][mgA + 4]);
                fma2(av2[3], kv, *(const ull*)&QsT[j][mgA + 6]);
            }
            #pragma unroll
            for (int i = 0; i < 4; i++) {
                float lo, hi; upk(av2[i], lo, hi);
                int mA = mgA + 2 * i;
                int sA = m0 + mA;
                float o0 = (mv && t <= sA)     ? __expf(lo * SCALE_ - ms[mA])     * il[mA]     : 0.0f;
                float o1 = (mv && t <= sA + 1) ? __expf(hi * SCALE_ - ms[mA + 1]) * il[mA + 1] : 0.0f;
                *(ull*)&As[kkA][mA] = pk(o0, o1);
            }
        }
        __syncthreads();
        #pragma unroll
        for (int kk = 0; kk < 16; kk++) {
            const ull* b64 = (const ull*)&Bs[buf][kk][tn * 8];
            ull bb0 = b64[0], bb1 = b64[1], bb2 = b64[2], bb3 = b64[3];
            float4 av0 = *(const float4*)&As[kk][tm * 8];
            float4 av1 = *(const float4*)&As[kk][tm * 8 + 4];
            ull a2_0 = pk2(av0.x), a2_1 = pk2(av0.y), a2_2 = pk2(av0.z), a2_3 = pk2(av0.w);
            ull a2_4 = pk2(av1.x), a2_5 = pk2(av1.y), a2_6 = pk2(av1.z), a2_7 = pk2(av1.w);
            fma2(acc2[0][0], a2_0, bb0); fma2(acc2[0][1], a2_0, bb1); fma2(acc2[0][2], a2_0, bb2); fma2(acc2[0][3], a2_0, bb3);
            fma2(acc2[1][0], a2_1, bb0); fma2(acc2[1][1], a2_1, bb1); fma2(acc2[1][2], a2_1, bb2); fma2(acc2[1][3], a2_1, bb3);
            fma2(acc2[2][0], a2_2, bb0); fma2(acc2[2][1], a2_2, bb1); fma2(acc2[2][2], a2_2, bb2); fma2(acc2[2][3], a2_2, bb3);
            fma2(acc2[3][0], a2_3, bb0); fma2(acc2[3][1], a2_3, bb1); fma2(acc2[3][2], a2_3, bb2); fma2(acc2[3][3], a2_3, bb3);
            fma2(acc2[4][0], a2_4, bb0); fma2(acc2[4][1], a2_4, bb1); fma2(acc2[4][2], a2_4, bb2); fma2(acc2[4][3], a2_4, bb3);
            fma2(acc2[5][0], a2_5, bb0); fma2(acc2[5][1], a2_5, bb1); fma2(acc2[5][2], a2_5, bb2); fma2(acc2[5][3], a2_5, bb3);
            fma2(acc2[6][0], a2_6, bb0); fma2(acc2[6][1], a2_6, bb1); fma2(acc2[6][2], a2_6, bb2); fma2(acc2[6][3], a2_6, bb3);
            fma2(acc2[7][0], a2_7, bb0); fma2(acc2[7][1], a2_7, bb1); fma2(acc2[7][2], a2_7, bb2); fma2(acc2[7][3], a2_7, bb3);
        }
        if (hasNext) {   // commit prefetched tiles to the other buffer
            int nbuf = buf ^ 1;
            if (tid < 128) {
                Ks[nbuf][krow][kj]     = nk.x; Ks[nbuf][krow][kj + 1] = nk.y;
                Ks[nbuf][krow][kj + 2] = nk.z; Ks[nbuf][krow][kj + 3] = nk.w;
            }
            *(float4*)&Bs[nbuf][brow][bn]     = nb0;
            *(float4*)&Bs[nbuf][brow][bn + 4] = nb1;
        }
        __syncthreads();
    }

    // epilogue: + b1, gelu, store to g_Y
    float bv[8];
    #pragma unroll
    for (int j = 0; j < 8; j++) bv[j] = b1[tn * 8 + j];
    #pragma unroll
    for (int i = 0; i < 8; i++) {
        int row = m0 + tm * 8 + i;
        float c0, c1, c2, c3, c4, c5, c6, c7;
        upk(acc2[i][0], c0, c1); upk(acc2[i][1], c2, c3);
        upk(acc2[i][2], c4, c5); upk(acc2[i][3], c6, c7);
        float4 o0 = make_float4(gelu_exact(c0 + bv[0]), gelu_exact(c1 + bv[1]),
                                gelu_exact(c2 + bv[2]), gelu_exact(c3 + bv[3]));
        float4 o1 = make_float4(gelu_exact(c4 + bv[4]), gelu_exact(c5 + bv[5]),
                                gelu_exact(c6 + bv[6]), gelu_exact(c7 + bv[7]));
        *(float4*)(Yout + (size_t)row * 128 + tn * 8)     = o0;
        *(float4*)(Yout + (size_t)row * 128 + tn * 8 + 4) = o1;
    }
}

// ---------------- K5: logits = Y @ W2^T + b2 ; d = argmax per digit ----------
__global__ void __launch_bounds__(256) head_kernel(int which,
                                                   const float* __restrict__ W2,
                                                   const float* __restrict__ b2,
                                                   float* __restrict__ dout,
                                                   float* __restrict__ lout) {
    const float* Y = g_Y + (size_t)which * BS_ * 128;
    int r0 = blockIdx.x * 16;
    int half = blockIdx.y;
    int cbase = half * 50;
    __shared__ float ys[16][128];
    __shared__ float ws[50][128];
    __shared__ float ls[16][52];
    int tid = threadIdx.x;
    {
        int row = tid >> 4, kq = (tid & 15) * 8;
        const float4* p = (const float4*)(Y + (size_t)(r0 + row) * 128 + kq);
        *(float4*)&ys[row][kq]     = p[0];
        *(float4*)&ys[row][kq + 4] = p[1];
    }
    for (int i4 = tid; i4 < 1600; i4 += 256) {
        int c = i4 >> 5, k4 = (i4 & 31) * 4;
        *(float4*)&ws[c][k4] = *(const float4*)(W2 + (size_t)(cbase + c) * 128 + k4);
    }
    __syncthreads();

    for (int idx = tid; idx < 800; idx += 256) {
        int row = idx / 50, c = idx - row * 50;
        float acc = b2[cbase + c];
        const float4* yp = (const float4*)ys[row];
        const float4* wp = (const float4*)ws[c];
        #pragma unroll
        for (int k = 0; k < 32; k++) {
            float4 yv = yp[k], wv = wp[k];
            acc += yv.x * wv.x + yv.y * wv.y + yv.z * wv.z + yv.w * wv.w;
        }
        ls[row][c] = acc;
        lout[(size_t)(r0 + row) * 100 + cbase + c] = acc;
    }
    __syncthreads();

    if (tid < 80) {
        int row = tid / 5, dg = tid - row * 5;
        float best = ls[row][dg * 10];
        int bi = 0;
        #pragma unroll
        for (int k = 1; k < 10; k++) {
            float v = ls[row][dg * 10 + k];
            if (v > best) { best = v; bi = k; }
        }
        dout[(size_t)(r0 + row) * 10 + half * 5 + dg] = (float)bi;
    }
}

// ---------------- launch (kernel launches ONLY — graph-capture safe) ---------
extern "C" void kernel_launch(void* const* d_in, const int* in_sizes, int n_in,
                              void* d_out, int out_size) {
    const float* h    = (const float*)d_in[0];
    const int*   mask = (const int*)  d_in[1];
    const float* Wq_a = (const float*)d_in[2];
    const float* Wk_a = (const float*)d_in[3];
    const float* Wq_b = (const float*)d_in[4];
    const float* Wk_b = (const float*)d_in[5];
    const float* W1_a = (const float*)d_in[6];
    const float* b1_a = (const float*)d_in[7];
    const float* W2_a = (const float*)d_in[8];
    const float* b2_a = (const float*)d_in[9];
    const float* W1_b = (const float*)d_in[10];
    const float* b1_b = (const float*)d_in[11];
    const float* W2_b = (const float*)d_in[12];
    const float* b2_b = (const float*)d_in[13];
    float* out = (float*)d_out;

    // K0: pack attention projection weights
    pack_w<<<(128 * H_ + 255) / 256, 256>>>(Wq_a, Wk_a, Wq_b, Wk_b);
    // K1: fused h@Wcat^T, h@W1_a^T, h@W1_b^T
    gemm_h128<<<dim3(BS_ / 64, 3), 256>>>(h, W1_a, W1_b);
    // K2: per-row softmax stats
    softmax_stats<<<dim3(S_ / 32, 8), 256>>>(mask);
    // K3: Y = gelu(P @ hW1 + b1) — P regenerated on the fly, causal-truncated
    gemm_pz<<<dim3(16, 8), 256>>>(mask, b1_a, b1_b);
    // K5: logits + STE argmax.  Output layout: [d_a | d_b | logits_a | logits_b]
    head_kernel<<<dim3(512, 2), 256>>>(0, W2_a, b2_a, out,         out + 163840);
    head_kernel<<<dim3(512, 2), 256>>>(1, W2_b, b2_b, out + 81920, out + 983040);
}